// round 2
// baseline (speedup 1.0000x reference)
#include <cuda_runtime.h>
#include <math.h>

// Problem constants
#define BB 8
#define CC 16
#define MM 32
#define KK 64
#define HH 384
#define WW 384
#define WF 193

// ---------------- scratch (device globals; no allocation allowed) ----------------
__device__ float2 g_Xr[(size_t)BB*CC*WF*HH];   // [b,c,w,h] complex
__device__ float2 g_Yf[(size_t)BB*KK*WF*HH];   // [b,k,w,h] complex
__device__ float2 g_tw[384];                   // exp(-2*pi*i*k/384)
__device__ float2 g_part[512];                 // partial (sum, sumsq)
__device__ float2 g_stats[8];                  // (mean, rstd) per batch

__device__ __forceinline__ float2 cmulf(float2 a, float2 b) {
    return make_float2(a.x*b.x - a.y*b.y, a.x*b.y + a.y*b.x);
}

// ---------------- small DFTs ----------------
template<int SIGN>
__device__ __forceinline__ void dft6(float2 v[6]) {
    const float S3 = 0.8660254037844386f * (float)SIGN;
    const float ct[6] = {1.f, 0.5f, -0.5f, -1.f, -0.5f, 0.5f};
    const float st[6] = {0.f, S3, S3, 0.f, -S3, -S3};
    float2 o[6];
#pragma unroll
    for (int r = 0; r < 6; r++) {
        float re = v[0].x, im = v[0].y;
#pragma unroll
        for (int j = 1; j < 6; j++) {
            const int k = (j*r) % 6;
            re += v[j].x*ct[k] - v[j].y*st[k];
            im += v[j].x*st[k] + v[j].y*ct[k];
        }
        o[r] = make_float2(re, im);
    }
#pragma unroll
    for (int r = 0; r < 6; r++) v[r] = o[r];
}

template<int SIGN>
__device__ __forceinline__ void dft8(float2 v[8]) {
    const float R2 = 0.70710678118654752f;
    const float S = (float)SIGN;
    const float ct[8] = {1.f, R2, 0.f, -R2, -1.f, -R2, 0.f, R2};
    const float st[8] = {0.f, R2*S, 1.f*S, R2*S, 0.f, -R2*S, -1.f*S, -R2*S};
    float2 o[8];
#pragma unroll
    for (int r = 0; r < 8; r++) {
        float re = v[0].x, im = v[0].y;
#pragma unroll
        for (int j = 1; j < 8; j++) {
            const int k = (j*r) & 7;
            re += v[j].x*ct[k] - v[j].y*st[k];
            im += v[j].x*st[k] + v[j].y*ct[k];
        }
        o[r] = make_float2(re, im);
    }
#pragma unroll
    for (int r = 0; r < 8; r++) v[r] = o[r];
}

// ---------------- 384-pt Stockham FFT: radix 6,8,8; result lands in pb ----------
template<int SIGN>
__device__ __forceinline__ void fft384(float2* pa, float2* pb, const float2* tw, int t) {
    __syncthreads();
    {   // stage 1: radix 6
        float2 v[6];
#pragma unroll
        for (int j = 0; j < 6; j++) v[j] = pa[t + 64*j];
        dft6<SIGN>(v);
#pragma unroll
        for (int r = 0; r < 6; r++) {
            float2 w = tw[t*r];
            if (SIGN > 0) w.y = -w.y;
            pb[6*t + r] = cmulf(v[r], w);
        }
    }
    __syncthreads();
    if (t < 48) {   // stage 2: radix 8
        const int q = t % 6, p = t / 6;
        float2 v[8];
#pragma unroll
        for (int j = 0; j < 8; j++) v[j] = pb[q + 6*(p + 8*j)];
        dft8<SIGN>(v);
#pragma unroll
        for (int r = 0; r < 8; r++) {
            float2 w = tw[6*p*r];
            if (SIGN > 0) w.y = -w.y;
            pa[q + 6*(8*p + r)] = cmulf(v[r], w);
        }
    }
    __syncthreads();
    if (t < 48) {   // stage 3: radix 8, twiddles = 1
        float2 v[8];
#pragma unroll
        for (int j = 0; j < 8; j++) v[j] = pa[t + 48*j];
        dft8<SIGN>(v);
#pragma unroll
        for (int r = 0; r < 8; r++) pb[t + 48*r] = v[r];
    }
    __syncthreads();
}

#define LSTR 390

// ---------------- twiddle init ----------------
__global__ void k_tw() {
    int i = threadIdx.x;
    if (i < 384) {
        float s, c;
        sincosf(-6.28318530717958647692f * (float)i / 384.f, &s, &c);
        g_tw[i] = make_float2(c, s);
    }
}

// ---------------- stats: per-batch mean / rstd ----------------
__global__ void k_stats1(const float* __restrict__ x) {
    const int b = blockIdx.x >> 6, sl = blockIdx.x & 63;
    const float4* p = (const float4*)x + (size_t)b*589824 + (size_t)sl*9216;
    float s = 0.f, q = 0.f;
    for (int i = threadIdx.x; i < 9216; i += 256) {
        float4 v = p[i];
        s += v.x + v.y + v.z + v.w;
        q += v.x*v.x + v.y*v.y + v.z*v.z + v.w*v.w;
    }
    __shared__ float rs[256], rq[256];
    rs[threadIdx.x] = s; rq[threadIdx.x] = q;
    __syncthreads();
    for (int o = 128; o > 0; o >>= 1) {
        if (threadIdx.x < o) { rs[threadIdx.x] += rs[threadIdx.x+o]; rq[threadIdx.x] += rq[threadIdx.x+o]; }
        __syncthreads();
    }
    if (threadIdx.x == 0) g_part[blockIdx.x] = make_float2(rs[0], rq[0]);
}

__global__ void k_stats2() {
    __shared__ float2 sp[512];
    sp[threadIdx.x] = g_part[threadIdx.x];
    __syncthreads();
    if (threadIdx.x < 8) {
        float s = 0.f, q = 0.f;
        for (int i = 0; i < 64; i++) { float2 v = sp[threadIdx.x*64 + i]; s += v.x; q += v.y; }
        const float Nb = (float)(CC*HH*WW);
        float mean = s / Nb;
        float var = q / Nb - mean*mean;
        g_stats[threadIdx.x] = make_float2(mean, rsqrtf(var + 1e-5f));
    }
}

// ---------------- forward rows: UNPACKED complex FFT per channel ---------------
// line = (b, c, h); pa[j] = (x[j], 0); store bins w in [0,193) to g_Xr[b,c,w,h].
__global__ void k_fwd_u(const float* __restrict__ x) {
    __shared__ float2 sa[4*LSTR], sb[4*LSTR], tw[384];
    for (int i = threadIdx.x; i < 384; i += 256) tw[i] = g_tw[i];
    const int l = threadIdx.x & 3, t = threadIdx.x >> 2;
    const int line = blockIdx.x*4 + l;                  // < 8*16*384
    const int h = line % 384;
    const int c = (line / 384) & 15;
    const int b = line / (384*16);
    const float* xr = x + (((size_t)(b*CC + c)*HH + h) * WW);
    float2* pa = sa + l*LSTR;
    float2* pb = sb + l*LSTR;
#pragma unroll
    for (int i = 0; i < 6; i++) { int j = t + 64*i; pa[j] = make_float2(xr[j], 0.f); }
    fft384<-1>(pa, pb, tw, t);
    for (int w = t; w < WF; w += 64) {
        g_Xr[((size_t)(b*CC + c)*WF + w)*HH + h] = pb[w];
    }
}

// ---------------- column FFTs (contiguous complex lines, in place) --------------
template<int SIGN, int WHICH>
__global__ void k_col() {
    __shared__ float2 sa[4*LSTR], sb[4*LSTR], tw[384];
    for (int i = threadIdx.x; i < 384; i += 256) tw[i] = g_tw[i];
    const int l = threadIdx.x & 3, t = threadIdx.x >> 2;
    const size_t line = (size_t)blockIdx.x*4 + l;
    float2* g = (WHICH == 0 ? g_Xr : g_Yf) + line*HH;
    float2* pa = sa + l*LSTR;
    float2* pb = sb + l*LSTR;
#pragma unroll
    for (int i = 0; i < 6; i++) { int j = t + 64*i; pa[j] = g[j]; }
    fft384<SIGN>(pa, pb, tw, t);
#pragma unroll
    for (int i = 0; i < 6; i++) { int j = t + 64*i; g[j] = pb[j]; }
}

// ---------------- mixing (unchanged from round 1) --------------------------------
__global__ void k_mix(const float* __restrict__ B_re, const float* __restrict__ B_im,
                      const float* __restrict__ C_re, const float* __restrict__ C_im,
                      const float* __restrict__ theta, const float* __restrict__ alpha_raw,
                      const float* __restrict__ beta,  const float* __restrict__ log_dc,
                      const float* __restrict__ log_tau, const float* __restrict__ log_scale,
                      const float* __restrict__ log_bw) {
    extern __shared__ float2 dyn[];
    float2* sT = dyn;            // [32][128]
    float2* sX = dyn + 4096;     // [16][128]
    float2* sZ = dyn + 6144;     // [32][128]
    __shared__ float2 sB[MM*CC];
    __shared__ float2 sC[KK*MM];
    __shared__ float  sPar[MM][8];

    const int tid = threadIdx.x;
    const int w = blockIdx.x / 3;
    const int h0 = (blockIdx.x % 3) * 128;

    for (int i = tid; i < MM*CC; i += 256) sB[i] = make_float2(B_re[i], B_im[i]);
    for (int i = tid; i < KK*MM; i += 256) sC[i] = make_float2(C_re[i], C_im[i]);
    if (tid < MM) {
        const int m = tid;
        float ar = alpha_raw[m];
        float spa = (ar > 20.f) ? ar : log1pf(expf(ar));
        float wc = expf(log_bw[m]);
        sPar[m][0] = spa;
        sPar[m][1] = beta[m];
        sPar[m][2] = expf(log_scale[m]);
        sPar[m][3] = expf(log_tau[m]);
        sPar[m][4] = expf(log_dc[m]);
        sPar[m][5] = 1.f / (wc*wc);
        sPar[m][6] = cosf(theta[m]);
        sPar[m][7] = sinf(theta[m]);
    }
    __syncthreads();

    const float TPN = 6.28318530717958647692f / 384.f;
    const float ox = (float)w * TPN;
    for (int e = tid; e < MM*128; e += 256) {
        const int m = e >> 7, p = e & 127, h = h0 + p;
        const float oy = (float)((h < 192) ? h : h - 384) * TPN;
        const float vd = sPar[m][6]*ox + sPar[m][7]*oy;
        const float w2 = ox*ox + oy*oy;
        const float wp2 = w2 - vd*vd;
        float Dre = sPar[m][0] + sPar[m][3]*wp2;
        float Dim = sPar[m][2]*vd - sPar[m][1];
        const float qq = w2 * sPar[m][5];
        const float q2 = qq*qq;
        const float bt = 1.f + q2*q2;
        Dre *= bt; Dim *= bt;
        const float inv = sPar[m][4] / (Dre*Dre + Dim*Dim);
        sT[e] = make_float2(Dre*inv, -Dim*inv);
    }
    __syncthreads();

    const float HWf = (float)(HH*WW);
    for (int b = 0; b < BB; b++) {
        const float mean = g_stats[b].x, rstd = g_stats[b].y;
        for (int e = tid; e < CC*128; e += 256) {
            const int c = e >> 7, p = e & 127;
            float2 v = g_Xr[((size_t)(b*CC + c)*WF + w)*HH + h0 + p];
            if (w == 0 && (h0 + p) == 0) v.x -= mean * HWf;
            v.x *= rstd; v.y *= rstd;
            sX[e] = v;
        }
        __syncthreads();
        for (int e = tid; e < MM*128; e += 256) {
            const int m = e >> 7, p = e & 127;
            float2 acc = make_float2(0.f, 0.f);
#pragma unroll
            for (int c = 0; c < CC; c++) {
                const float2 bv = sB[m*CC + c];
                const float2 xv = sX[c*128 + p];
                acc.x += bv.x*xv.x - bv.y*xv.y;
                acc.y += bv.x*xv.y + bv.y*xv.x;
            }
            sZ[e] = cmulf(acc, sT[e]);
        }
        __syncthreads();
        {
            const int p = tid & 127, kh = tid >> 7;
            for (int kk0 = 0; kk0 < 32; kk0 += 8) {
                float2 acc[8];
#pragma unroll
                for (int j = 0; j < 8; j++) acc[j] = make_float2(0.f, 0.f);
#pragma unroll 4
                for (int m = 0; m < MM; m++) {
                    const float2 zv = sZ[m*128 + p];
#pragma unroll
                    for (int j = 0; j < 8; j++) {
                        const float2 cv = sC[(kh*32 + kk0 + j)*MM + m];
                        acc[j].x += cv.x*zv.x - cv.y*zv.y;
                        acc[j].y += cv.x*zv.y + cv.y*zv.x;
                    }
                }
#pragma unroll
                for (int j = 0; j < 8; j++) {
                    const int k = kh*32 + kk0 + j;
                    g_Yf[((size_t)(b*KK + k)*WF + w)*HH + h0 + p] = acc[j];
                }
            }
        }
        __syncthreads();
    }
}

// ---------------- inverse rows: UNPACKED, one output channel per line -----------
// line = (b, k, h). Full row spectrum: F[w] = Y[w] (w<193), conj(Y[384-w]) (w>192).
// No special-casing of bins 0/192: taking Re() of the inverse FFT is exactly
// equivalent to irfft's imag-drop convention.
__global__ void k_inv_u(float* __restrict__ y) {
    __shared__ float2 sa[4*LSTR], sb[4*LSTR], tw[384];
    for (int i = threadIdx.x; i < 384; i += 256) tw[i] = g_tw[i];
    const int l = threadIdx.x & 3, t = threadIdx.x >> 2;
    const int line = blockIdx.x*4 + l;                 // < 8*64*384
    const int h = line % 384;
    const int k = (line / 384) & 63;
    const int b = line / (384*64);
    const size_t base = ((size_t)(b*KK + k)*WF)*HH + h;
    float2* pa = sa + l*LSTR;
    float2* pb = sb + l*LSTR;
#pragma unroll
    for (int i = 0; i < 6; i++) {
        const int w = t + 64*i;
        if (w < WF) {
            pa[w] = g_Yf[base + (size_t)w*HH];
        } else {
            float2 v = g_Yf[base + (size_t)(384 - w)*HH];
            pa[w] = make_float2(v.x, -v.y);
        }
    }
    fft384<1>(pa, pb, tw, t);
    const float sc = 1.f / (float)(HH*WW);
    float* o = y + ((size_t)(b*KK + k)*HH + h) * WW;
#pragma unroll
    for (int i = 0; i < 6; i++) {
        const int j = t + 64*i;
        o[j] = pb[j].x * sc;
    }
}

// ---------------- launch ----------------
extern "C" void kernel_launch(void* const* d_in, const int* in_sizes, int n_in,
                              void* d_out, int out_size) {
    const float* x         = (const float*)d_in[0];
    const float* theta     = (const float*)d_in[1];
    const float* B_re      = (const float*)d_in[2];
    const float* B_im      = (const float*)d_in[3];
    const float* C_re      = (const float*)d_in[4];
    const float* C_im      = (const float*)d_in[5];
    const float* alpha_raw = (const float*)d_in[6];
    const float* beta      = (const float*)d_in[7];
    const float* log_dc    = (const float*)d_in[8];
    const float* log_tau   = (const float*)d_in[9];
    const float* log_scale = (const float*)d_in[10];
    const float* log_bw    = (const float*)d_in[11];
    float* y = (float*)d_out;

    cudaFuncSetAttribute(k_mix, cudaFuncAttributeMaxDynamicSharedMemorySize, 81920);

    k_tw<<<1, 384>>>();
    k_stats1<<<512, 256>>>(x);
    k_stats2<<<1, 512>>>();
    k_fwd_u<<<(BB*CC*HH)/4, 256>>>(x);                  // 12288 blocks
    k_col<-1, 0><<<(BB*CC*WF)/4, 256>>>();              // 6176 blocks
    k_mix<<<WF*3, 256, 81920>>>(B_re, B_im, C_re, C_im, theta, alpha_raw, beta,
                                log_dc, log_tau, log_scale, log_bw);
    k_col<1, 1><<<(BB*KK*WF)/4, 256>>>();               // 24704 blocks
    k_inv_u<<<(BB*KK*HH)/4, 256>>>(y);                  // 49152 blocks
}

// round 3
// speedup vs baseline: 1.1286x; 1.1286x over previous
#include <cuda_runtime.h>
#include <math.h>

// Problem constants
#define BB 8
#define CC 16
#define MM 32
#define KK 64
#define HH 384
#define WW 384
#define WF 193

// ---------------- scratch (device globals; no allocation allowed) ----------------
__device__ float2 g_Xr[(size_t)BB*CC*WF*HH];   // [b,c,w,h] complex
__device__ float2 g_Yf[(size_t)BB*KK*WF*HH];   // [b,k,w,h] complex
__device__ float2 g_tw[384];                   // exp(-2*pi*i*k/384)
__device__ float2 g_part[512];                 // partial (sum, sumsq)
__device__ float2 g_stats[8];                  // (mean, rstd) per batch

__device__ __forceinline__ float2 cmulf(float2 a, float2 b) {
    return make_float2(a.x*b.x - a.y*b.y, a.x*b.y + a.y*b.x);
}

// ---------------- small DFTs ----------------
template<int SIGN>
__device__ __forceinline__ void dft6(float2 v[6]) {
    const float S3 = 0.8660254037844386f * (float)SIGN;
    const float ct[6] = {1.f, 0.5f, -0.5f, -1.f, -0.5f, 0.5f};
    const float st[6] = {0.f, S3, S3, 0.f, -S3, -S3};
    float2 o[6];
#pragma unroll
    for (int r = 0; r < 6; r++) {
        float re = v[0].x, im = v[0].y;
#pragma unroll
        for (int j = 1; j < 6; j++) {
            const int k = (j*r) % 6;
            re += v[j].x*ct[k] - v[j].y*st[k];
            im += v[j].x*st[k] + v[j].y*ct[k];
        }
        o[r] = make_float2(re, im);
    }
#pragma unroll
    for (int r = 0; r < 6; r++) v[r] = o[r];
}

template<int SIGN>
__device__ __forceinline__ void dft8(float2 v[8]) {
    const float R2 = 0.70710678118654752f;
    const float S = (float)SIGN;
    const float ct[8] = {1.f, R2, 0.f, -R2, -1.f, -R2, 0.f, R2};
    const float st[8] = {0.f, R2*S, 1.f*S, R2*S, 0.f, -R2*S, -1.f*S, -R2*S};
    float2 o[8];
#pragma unroll
    for (int r = 0; r < 8; r++) {
        float re = v[0].x, im = v[0].y;
#pragma unroll
        for (int j = 1; j < 8; j++) {
            const int k = (j*r) & 7;
            re += v[j].x*ct[k] - v[j].y*st[k];
            im += v[j].x*st[k] + v[j].y*ct[k];
        }
        o[r] = make_float2(re, im);
    }
#pragma unroll
    for (int r = 0; r < 8; r++) v[r] = o[r];
}

// ---------------- 384-pt Stockham FFT: radix 6,8,8; result lands in pb ----------
template<int SIGN>
__device__ __forceinline__ void fft384(float2* pa, float2* pb, const float2* tw, int t) {
    __syncthreads();
    {   // stage 1: radix 6
        float2 v[6];
#pragma unroll
        for (int j = 0; j < 6; j++) v[j] = pa[t + 64*j];
        dft6<SIGN>(v);
#pragma unroll
        for (int r = 0; r < 6; r++) {
            float2 w = tw[t*r];
            if (SIGN > 0) w.y = -w.y;
            pb[6*t + r] = cmulf(v[r], w);
        }
    }
    __syncthreads();
    if (t < 48) {   // stage 2: radix 8
        const int q = t % 6, p = t / 6;
        float2 v[8];
#pragma unroll
        for (int j = 0; j < 8; j++) v[j] = pb[q + 6*(p + 8*j)];
        dft8<SIGN>(v);
#pragma unroll
        for (int r = 0; r < 8; r++) {
            float2 w = tw[6*p*r];
            if (SIGN > 0) w.y = -w.y;
            pa[q + 6*(8*p + r)] = cmulf(v[r], w);
        }
    }
    __syncthreads();
    if (t < 48) {   // stage 3: radix 8, twiddles = 1
        float2 v[8];
#pragma unroll
        for (int j = 0; j < 8; j++) v[j] = pa[t + 48*j];
        dft8<SIGN>(v);
#pragma unroll
        for (int r = 0; r < 8; r++) pb[t + 48*r] = v[r];
    }
    __syncthreads();
}

#define LSTR 390

// ---------------- twiddle init ----------------
__global__ void k_tw() {
    int i = threadIdx.x;
    if (i < 384) {
        float s, c;
        sincosf(-6.28318530717958647692f * (float)i / 384.f, &s, &c);
        g_tw[i] = make_float2(c, s);
    }
}

// ---------------- stats: per-batch mean / rstd ----------------
__global__ void k_stats1(const float* __restrict__ x) {
    const int b = blockIdx.x >> 6, sl = blockIdx.x & 63;
    const float4* p = (const float4*)x + (size_t)b*589824 + (size_t)sl*9216;
    float s = 0.f, q = 0.f;
    for (int i = threadIdx.x; i < 9216; i += 256) {
        float4 v = p[i];
        s += v.x + v.y + v.z + v.w;
        q += v.x*v.x + v.y*v.y + v.z*v.z + v.w*v.w;
    }
    __shared__ float rs[256], rq[256];
    rs[threadIdx.x] = s; rq[threadIdx.x] = q;
    __syncthreads();
    for (int o = 128; o > 0; o >>= 1) {
        if (threadIdx.x < o) { rs[threadIdx.x] += rs[threadIdx.x+o]; rq[threadIdx.x] += rq[threadIdx.x+o]; }
        __syncthreads();
    }
    if (threadIdx.x == 0) g_part[blockIdx.x] = make_float2(rs[0], rq[0]);
}

__global__ void k_stats2() {
    __shared__ float2 sp[512];
    sp[threadIdx.x] = g_part[threadIdx.x];
    __syncthreads();
    if (threadIdx.x < 8) {
        float s = 0.f, q = 0.f;
        for (int i = 0; i < 64; i++) { float2 v = sp[threadIdx.x*64 + i]; s += v.x; q += v.y; }
        const float Nb = (float)(CC*HH*WW);
        float mean = s / Nb;
        float var = q / Nb - mean*mean;
        g_stats[threadIdx.x] = make_float2(mean, rsqrtf(var + 1e-5f));
    }
}

// ---------------- forward rows: UNPACKED complex FFT per channel ---------------
__global__ void k_fwd_u(const float* __restrict__ x) {
    __shared__ float2 sa[4*LSTR], sb[4*LSTR], tw[384];
    for (int i = threadIdx.x; i < 384; i += 256) tw[i] = g_tw[i];
    const int l = threadIdx.x & 3, t = threadIdx.x >> 2;
    const int line = blockIdx.x*4 + l;                  // < 8*16*384
    const int h = line % 384;
    const int c = (line / 384) & 15;
    const int b = line / (384*16);
    const float* xr = x + (((size_t)(b*CC + c)*HH + h) * WW);
    float2* pa = sa + l*LSTR;
    float2* pb = sb + l*LSTR;
#pragma unroll
    for (int i = 0; i < 6; i++) { int j = t + 64*i; pa[j] = make_float2(xr[j], 0.f); }
    fft384<-1>(pa, pb, tw, t);
    for (int w = t; w < WF; w += 64) {
        g_Xr[((size_t)(b*CC + c)*WF + w)*HH + h] = pb[w];
    }
}

// ---------------- column FFTs (contiguous complex lines, in place) --------------
template<int SIGN, int WHICH>
__global__ void k_col() {
    __shared__ float2 sa[4*LSTR], sb[4*LSTR], tw[384];
    for (int i = threadIdx.x; i < 384; i += 256) tw[i] = g_tw[i];
    const int l = threadIdx.x & 3, t = threadIdx.x >> 2;
    const size_t line = (size_t)blockIdx.x*4 + l;
    float2* g = (WHICH == 0 ? g_Xr : g_Yf) + line*HH;
    float2* pa = sa + l*LSTR;
    float2* pb = sb + l*LSTR;
#pragma unroll
    for (int i = 0; i < 6; i++) { int j = t + 64*i; pa[j] = g[j]; }
    fft384<SIGN>(pa, pb, tw, t);
#pragma unroll
    for (int i = 0; i < 6; i++) { int j = t + 64*i; g[j] = pb[j]; }
}

// ---------------- mixing (unchanged) ---------------------------------------------
__global__ void k_mix(const float* __restrict__ B_re, const float* __restrict__ B_im,
                      const float* __restrict__ C_re, const float* __restrict__ C_im,
                      const float* __restrict__ theta, const float* __restrict__ alpha_raw,
                      const float* __restrict__ beta,  const float* __restrict__ log_dc,
                      const float* __restrict__ log_tau, const float* __restrict__ log_scale,
                      const float* __restrict__ log_bw) {
    extern __shared__ float2 dyn[];
    float2* sT = dyn;            // [32][128]
    float2* sX = dyn + 4096;     // [16][128]
    float2* sZ = dyn + 6144;     // [32][128]
    __shared__ float2 sB[MM*CC];
    __shared__ float2 sC[KK*MM];
    __shared__ float  sPar[MM][8];

    const int tid = threadIdx.x;
    const int w = blockIdx.x / 3;
    const int h0 = (blockIdx.x % 3) * 128;

    for (int i = tid; i < MM*CC; i += 256) sB[i] = make_float2(B_re[i], B_im[i]);
    for (int i = tid; i < KK*MM; i += 256) sC[i] = make_float2(C_re[i], C_im[i]);
    if (tid < MM) {
        const int m = tid;
        float ar = alpha_raw[m];
        float spa = (ar > 20.f) ? ar : log1pf(expf(ar));
        float wc = expf(log_bw[m]);
        sPar[m][0] = spa;
        sPar[m][1] = beta[m];
        sPar[m][2] = expf(log_scale[m]);
        sPar[m][3] = expf(log_tau[m]);
        sPar[m][4] = expf(log_dc[m]);
        sPar[m][5] = 1.f / (wc*wc);
        sPar[m][6] = cosf(theta[m]);
        sPar[m][7] = sinf(theta[m]);
    }
    __syncthreads();

    const float TPN = 6.28318530717958647692f / 384.f;
    const float ox = (float)w * TPN;
    for (int e = tid; e < MM*128; e += 256) {
        const int m = e >> 7, p = e & 127, h = h0 + p;
        const float oy = (float)((h < 192) ? h : h - 384) * TPN;
        const float vd = sPar[m][6]*ox + sPar[m][7]*oy;
        const float w2 = ox*ox + oy*oy;
        const float wp2 = w2 - vd*vd;
        float Dre = sPar[m][0] + sPar[m][3]*wp2;
        float Dim = sPar[m][2]*vd - sPar[m][1];
        const float qq = w2 * sPar[m][5];
        const float q2 = qq*qq;
        const float bt = 1.f + q2*q2;
        Dre *= bt; Dim *= bt;
        const float inv = sPar[m][4] / (Dre*Dre + Dim*Dim);
        sT[e] = make_float2(Dre*inv, -Dim*inv);
    }
    __syncthreads();

    const float HWf = (float)(HH*WW);
    for (int b = 0; b < BB; b++) {
        const float mean = g_stats[b].x, rstd = g_stats[b].y;
        for (int e = tid; e < CC*128; e += 256) {
            const int c = e >> 7, p = e & 127;
            float2 v = g_Xr[((size_t)(b*CC + c)*WF + w)*HH + h0 + p];
            if (w == 0 && (h0 + p) == 0) v.x -= mean * HWf;
            v.x *= rstd; v.y *= rstd;
            sX[e] = v;
        }
        __syncthreads();
        for (int e = tid; e < MM*128; e += 256) {
            const int m = e >> 7, p = e & 127;
            float2 acc = make_float2(0.f, 0.f);
#pragma unroll
            for (int c = 0; c < CC; c++) {
                const float2 bv = sB[m*CC + c];
                const float2 xv = sX[c*128 + p];
                acc.x += bv.x*xv.x - bv.y*xv.y;
                acc.y += bv.x*xv.y + bv.y*xv.x;
            }
            sZ[e] = cmulf(acc, sT[e]);
        }
        __syncthreads();
        {
            const int p = tid & 127, kh = tid >> 7;
            for (int kk0 = 0; kk0 < 32; kk0 += 8) {
                float2 acc[8];
#pragma unroll
                for (int j = 0; j < 8; j++) acc[j] = make_float2(0.f, 0.f);
#pragma unroll 4
                for (int m = 0; m < MM; m++) {
                    const float2 zv = sZ[m*128 + p];
#pragma unroll
                    for (int j = 0; j < 8; j++) {
                        const float2 cv = sC[(kh*32 + kk0 + j)*MM + m];
                        acc[j].x += cv.x*zv.x - cv.y*zv.y;
                        acc[j].y += cv.x*zv.y + cv.y*zv.x;
                    }
                }
#pragma unroll
                for (int j = 0; j < 8; j++) {
                    const int k = kh*32 + kk0 + j;
                    g_Yf[((size_t)(b*KK + k)*WF + w)*HH + h0 + p] = acc[j];
                }
            }
        }
        __syncthreads();
    }
}

// ---------------- inverse rows: PACKED (2 output channels per complex IFFT) -----
// line-pair = (b, kp, h). Q1/Q2 are column-transformed spectra of channels
// 2kp / 2kp+1. Build z[w] = R1[w] + i*R2[w] with Hermitian extension in w and the
// pocketfft c2r convention at the self-conjugate bins w=0,192 (imag dropped):
//   w==0 or 192:  z = Re(Q1[w])   + i*Re(Q2[w])
//   0<w<193:      z = Q1[w]       + i*Q2[w]
//   w>192:        z = conj(Q1[384-w]) + i*conj(Q2[384-w])
// Then y1 = Re(ifft(z))/N^2, y2 = Im(ifft(z))/N^2.
__global__ void k_inv_p(float* __restrict__ y) {
    __shared__ float2 sa[4*LSTR], sb[4*LSTR], tw[384];
    for (int i = threadIdx.x; i < 384; i += 256) tw[i] = g_tw[i];
    const int l = threadIdx.x & 3, t = threadIdx.x >> 2;
    const int line = blockIdx.x*4 + l;                 // < 8*32*384
    const int h = line % 384;
    const int kp = (line / 384) & 31;
    const int b = line / (384*32);
    const size_t base1 = ((size_t)(b*KK + 2*kp)*WF)*HH + h;
    const size_t base2 = base1 + (size_t)WF*HH;
    float2* pa = sa + l*LSTR;
    float2* pb = sb + l*LSTR;
#pragma unroll
    for (int i = 0; i < 6; i++) {
        const int w = t + 64*i;
        const int wi = (w < WF) ? w : (384 - w);
        const float2 q1 = g_Yf[base1 + (size_t)wi*HH];
        const float2 q2 = g_Yf[base2 + (size_t)wi*HH];
        float2 z;
        if (w == 0 || w == 192) {
            z = make_float2(q1.x, q2.x);                 // c2r drops imag at 0 & Nyquist
        } else if (w < WF) {
            z = make_float2(q1.x - q2.y, q1.y + q2.x);   // Q1 + i*Q2
        } else {
            z = make_float2(q1.x + q2.y, q2.x - q1.y);   // conj(Q1) + i*conj(Q2)
        }
        pa[w] = z;
    }
    fft384<1>(pa, pb, tw, t);
    const float sc = 1.f / (float)(HH*WW);
    float* o1 = y + ((size_t)(b*KK + 2*kp)*HH + h) * WW;
    float* o2 = o1 + (size_t)HH*WW;
#pragma unroll
    for (int i = 0; i < 6; i++) {
        const int j = t + 64*i;
        const float2 v = pb[j];
        o1[j] = v.x * sc;
        o2[j] = v.y * sc;
    }
}

// ---------------- launch ----------------
extern "C" void kernel_launch(void* const* d_in, const int* in_sizes, int n_in,
                              void* d_out, int out_size) {
    const float* x         = (const float*)d_in[0];
    const float* theta     = (const float*)d_in[1];
    const float* B_re      = (const float*)d_in[2];
    const float* B_im      = (const float*)d_in[3];
    const float* C_re      = (const float*)d_in[4];
    const float* C_im      = (const float*)d_in[5];
    const float* alpha_raw = (const float*)d_in[6];
    const float* beta      = (const float*)d_in[7];
    const float* log_dc    = (const float*)d_in[8];
    const float* log_tau   = (const float*)d_in[9];
    const float* log_scale = (const float*)d_in[10];
    const float* log_bw    = (const float*)d_in[11];
    float* y = (float*)d_out;

    cudaFuncSetAttribute(k_mix, cudaFuncAttributeMaxDynamicSharedMemorySize, 81920);

    k_tw<<<1, 384>>>();
    k_stats1<<<512, 256>>>(x);
    k_stats2<<<1, 512>>>();
    k_fwd_u<<<(BB*CC*HH)/4, 256>>>(x);                  // 12288 blocks
    k_col<-1, 0><<<(BB*CC*WF)/4, 256>>>();              // 6176 blocks
    k_mix<<<WF*3, 256, 81920>>>(B_re, B_im, C_re, C_im, theta, alpha_raw, beta,
                                log_dc, log_tau, log_scale, log_bw);
    k_col<1, 1><<<(BB*KK*WF)/4, 256>>>();               // 24704 blocks
    k_inv_p<<<(BB*MM*HH)/4, 256>>>(y);                  // 24576 blocks (packed pairs)
}

// round 5
// speedup vs baseline: 1.3742x; 1.2176x over previous
#include <cuda_runtime.h>
#include <math.h>

// Problem constants
#define BB 8
#define CC 16
#define MM 32
#define KK 64
#define HH 384
#define WW 384
#define WF 193

// ---------------- scratch (device globals; no allocation allowed) ----------------
__device__ float2 g_Xr[(size_t)BB*CC*WF*HH];   // [b,c,w,h] complex (75.9 MB)
__device__ float2 g_Z [(size_t)BB*MM*WF*HH];   // [b,m,w,h] complex (151.8 MB)
__device__ float2 g_Yf[(size_t)BB*KK*WF*HH];   // [b,k,w,h] complex (303.6 MB)
__device__ float2 g_tw[384];
__device__ float2 g_part[512];
__device__ float2 g_stats[8];

__device__ __forceinline__ float2 cmulf(float2 a, float2 b) {
    return make_float2(a.x*b.x - a.y*b.y, a.x*b.y + a.y*b.x);
}
__device__ __forceinline__ void cfma(float2& acc, float2 a, float2 b) {
    acc.x += a.x*b.x; acc.x -= a.y*b.y;
    acc.y += a.x*b.y; acc.y += a.y*b.x;
}

// ---------------- small DFTs ----------------
template<int SIGN>
__device__ __forceinline__ void dft6(float2 v[6]) {
    const float S3 = 0.8660254037844386f * (float)SIGN;
    const float ct[6] = {1.f, 0.5f, -0.5f, -1.f, -0.5f, 0.5f};
    const float st[6] = {0.f, S3, S3, 0.f, -S3, -S3};
    float2 o[6];
#pragma unroll
    for (int r = 0; r < 6; r++) {
        float re = v[0].x, im = v[0].y;
#pragma unroll
        for (int j = 1; j < 6; j++) {
            const int k = (j*r) % 6;
            re += v[j].x*ct[k] - v[j].y*st[k];
            im += v[j].x*st[k] + v[j].y*ct[k];
        }
        o[r] = make_float2(re, im);
    }
#pragma unroll
    for (int r = 0; r < 6; r++) v[r] = o[r];
}

template<int SIGN>
__device__ __forceinline__ void dft8(float2 v[8]) {
    const float R2 = 0.70710678118654752f;
    const float S = (float)SIGN;
    const float ct[8] = {1.f, R2, 0.f, -R2, -1.f, -R2, 0.f, R2};
    const float st[8] = {0.f, R2*S, 1.f*S, R2*S, 0.f, -R2*S, -1.f*S, -R2*S};
    float2 o[8];
#pragma unroll
    for (int r = 0; r < 8; r++) {
        float re = v[0].x, im = v[0].y;
#pragma unroll
        for (int j = 1; j < 8; j++) {
            const int k = (j*r) & 7;
            re += v[j].x*ct[k] - v[j].y*st[k];
            im += v[j].x*st[k] + v[j].y*ct[k];
        }
        o[r] = make_float2(re, im);
    }
#pragma unroll
    for (int r = 0; r < 8; r++) v[r] = o[r];
}

// ---------------- 384-pt Stockham FFT: radix 6,8,8; result lands in pb ----------
template<int SIGN>
__device__ __forceinline__ void fft384(float2* pa, float2* pb, const float2* tw, int t) {
    __syncthreads();
    {
        float2 v[6];
#pragma unroll
        for (int j = 0; j < 6; j++) v[j] = pa[t + 64*j];
        dft6<SIGN>(v);
#pragma unroll
        for (int r = 0; r < 6; r++) {
            float2 w = tw[t*r];
            if (SIGN > 0) w.y = -w.y;
            pb[6*t + r] = cmulf(v[r], w);
        }
    }
    __syncthreads();
    if (t < 48) {
        const int q = t % 6, p = t / 6;
        float2 v[8];
#pragma unroll
        for (int j = 0; j < 8; j++) v[j] = pb[q + 6*(p + 8*j)];
        dft8<SIGN>(v);
#pragma unroll
        for (int r = 0; r < 8; r++) {
            float2 w = tw[6*p*r];
            if (SIGN > 0) w.y = -w.y;
            pa[q + 6*(8*p + r)] = cmulf(v[r], w);
        }
    }
    __syncthreads();
    if (t < 48) {
        float2 v[8];
#pragma unroll
        for (int j = 0; j < 8; j++) v[j] = pa[t + 48*j];
        dft8<SIGN>(v);
#pragma unroll
        for (int r = 0; r < 8; r++) pb[t + 48*r] = v[r];
    }
    __syncthreads();
}

#define LSTR 390

// ---------------- twiddle init ----------------
__global__ void k_tw() {
    int i = threadIdx.x;
    if (i < 384) {
        float s, c;
        sincosf(-6.28318530717958647692f * (float)i / 384.f, &s, &c);
        g_tw[i] = make_float2(c, s);
    }
}

// ---------------- stats ----------------
__global__ void k_stats1(const float* __restrict__ x) {
    const int b = blockIdx.x >> 6, sl = blockIdx.x & 63;
    const float4* p = (const float4*)x + (size_t)b*589824 + (size_t)sl*9216;
    float s = 0.f, q = 0.f;
    for (int i = threadIdx.x; i < 9216; i += 256) {
        float4 v = p[i];
        s += v.x + v.y + v.z + v.w;
        q += v.x*v.x + v.y*v.y + v.z*v.z + v.w*v.w;
    }
    __shared__ float rs[256], rq[256];
    rs[threadIdx.x] = s; rq[threadIdx.x] = q;
    __syncthreads();
    for (int o = 128; o > 0; o >>= 1) {
        if (threadIdx.x < o) { rs[threadIdx.x] += rs[threadIdx.x+o]; rq[threadIdx.x] += rq[threadIdx.x+o]; }
        __syncthreads();
    }
    if (threadIdx.x == 0) g_part[blockIdx.x] = make_float2(rs[0], rq[0]);
}

__global__ void k_stats2() {
    __shared__ float2 sp[512];
    sp[threadIdx.x] = g_part[threadIdx.x];
    __syncthreads();
    if (threadIdx.x < 8) {
        float s = 0.f, q = 0.f;
        for (int i = 0; i < 64; i++) { float2 v = sp[threadIdx.x*64 + i]; s += v.x; q += v.y; }
        const float Nb = (float)(CC*HH*WW);
        float mean = s / Nb;
        float var = q / Nb - mean*mean;
        g_stats[threadIdx.x] = make_float2(mean, rsqrtf(var + 1e-5f));
    }
}

// ---------------- forward rows (unpacked) ---------------------------------------
__global__ void k_fwd_u(const float* __restrict__ x) {
    __shared__ float2 sa[4*LSTR], sb[4*LSTR], tw[384];
    for (int i = threadIdx.x; i < 384; i += 256) tw[i] = g_tw[i];
    const int l = threadIdx.x & 3, t = threadIdx.x >> 2;
    const int line = blockIdx.x*4 + l;
    const int h = line % 384;
    const int c = (line / 384) & 15;
    const int b = line / (384*16);
    const float* xr = x + (((size_t)(b*CC + c)*HH + h) * WW);
    float2* pa = sa + l*LSTR;
    float2* pb = sb + l*LSTR;
#pragma unroll
    for (int i = 0; i < 6; i++) { int j = t + 64*i; pa[j] = make_float2(xr[j], 0.f); }
    fft384<-1>(pa, pb, tw, t);
    for (int w = t; w < WF; w += 64) {
        g_Xr[((size_t)(b*CC + c)*WF + w)*HH + h] = pb[w];
    }
}

// ---------------- column FFTs (WHICH: 0=g_Xr, 1=g_Yf, 2=g_Z) --------------------
template<int SIGN, int WHICH>
__global__ void k_col() {
    __shared__ float2 sa[4*LSTR], sb[4*LSTR], tw[384];
    for (int i = threadIdx.x; i < 384; i += 256) tw[i] = g_tw[i];
    const int l = threadIdx.x & 3, t = threadIdx.x >> 2;
    const size_t line = (size_t)blockIdx.x*4 + l;
    float2* g = (WHICH == 0 ? g_Xr : (WHICH == 1 ? g_Yf : g_Z)) + line*HH;
    float2* pa = sa + l*LSTR;
    float2* pb = sb + l*LSTR;
#pragma unroll
    for (int i = 0; i < 6; i++) { int j = t + 64*i; pa[j] = g[j]; }
    fft384<SIGN>(pa, pb, tw, t);
#pragma unroll
    for (int i = 0; i < 6; i++) { int j = t + 64*i; g[j] = pb[j]; }
}

// ---------------- mixZ: Z = (B @ Xf_norm) * T, register-blocked GEMM -------------
__global__ void k_mixZ(const float* __restrict__ B_re, const float* __restrict__ B_im,
                       const float* __restrict__ theta, const float* __restrict__ alpha_raw,
                       const float* __restrict__ beta,  const float* __restrict__ log_dc,
                       const float* __restrict__ log_tau, const float* __restrict__ log_scale,
                       const float* __restrict__ log_bw) {
    extern __shared__ float2 dyn[];
    float2* sT = dyn;           // [32][128]
    float2* sX = dyn + 4096;    // [16][128]
    __shared__ float2 sBt[CC*MM];   // [c][m]
    __shared__ float  sPar[MM][8];

    const int tid = threadIdx.x;
    const int w = blockIdx.x / 3;
    const int h0 = (blockIdx.x % 3) * 128;

    for (int i = tid; i < CC*MM; i += 256) {
        const int c = i >> 5, m = i & 31;
        sBt[i] = make_float2(B_re[m*CC + c], B_im[m*CC + c]);
    }
    if (tid < MM) {
        const int m = tid;
        float ar = alpha_raw[m];
        float spa = (ar > 20.f) ? ar : log1pf(expf(ar));
        float wc = expf(log_bw[m]);
        sPar[m][0] = spa;
        sPar[m][1] = beta[m];
        sPar[m][2] = expf(log_scale[m]);
        sPar[m][3] = expf(log_tau[m]);
        sPar[m][4] = expf(log_dc[m]);
        sPar[m][5] = 1.f / (wc*wc);
        sPar[m][6] = cosf(theta[m]);
        sPar[m][7] = sinf(theta[m]);
    }
    __syncthreads();

    const float TPN = 6.28318530717958647692f / 384.f;
    const float ox = (float)w * TPN;
    for (int e = tid; e < MM*128; e += 256) {
        const int m = e >> 7, p = e & 127, h = h0 + p;
        const float oy = (float)((h < 192) ? h : h - 384) * TPN;
        const float vd = sPar[m][6]*ox + sPar[m][7]*oy;
        const float w2 = ox*ox + oy*oy;
        const float wp2 = w2 - vd*vd;
        float Dre = sPar[m][0] + sPar[m][3]*wp2;
        float Dim = sPar[m][2]*vd - sPar[m][1];
        const float qq = w2 * sPar[m][5];
        const float q2 = qq*qq;
        const float bt = 1.f + q2*q2;
        Dre *= bt; Dim *= bt;
        const float inv = sPar[m][4] / (Dre*Dre + Dim*Dim);
        sT[e] = make_float2(Dre*inv, -Dim*inv);
    }
    __syncthreads();

    const int warp = tid >> 5, lane = tid & 31;
    const int m0 = warp * 4;
    const float HWf = (float)(HH*WW);

    for (int b = 0; b < BB; b++) {
        const float mean = g_stats[b].x, rstd = g_stats[b].y;
        for (int e = tid; e < CC*128; e += 256) {
            const int c = e >> 7, p = e & 127;
            float2 v = g_Xr[((size_t)(b*CC + c)*WF + w)*HH + h0 + p];
            if (w == 0 && (h0 + p) == 0) v.x -= mean * HWf;
            v.x *= rstd; v.y *= rstd;
            sX[e] = v;
        }
        __syncthreads();

        float2 acc[4][4];
#pragma unroll
        for (int mm = 0; mm < 4; mm++)
#pragma unroll
            for (int j = 0; j < 4; j++) acc[mm][j] = make_float2(0.f, 0.f);

#pragma unroll
        for (int c = 0; c < CC; c++) {
            float2 bv[4], xv[4];
#pragma unroll
            for (int mm = 0; mm < 4; mm++) bv[mm] = sBt[c*32 + m0 + mm];
#pragma unroll
            for (int j = 0; j < 4; j++) xv[j] = sX[c*128 + lane + 32*j];
#pragma unroll
            for (int mm = 0; mm < 4; mm++)
#pragma unroll
                for (int j = 0; j < 4; j++) cfma(acc[mm][j], bv[mm], xv[j]);
        }
#pragma unroll
        for (int mm = 0; mm < 4; mm++) {
            const int m = m0 + mm;
#pragma unroll
            for (int j = 0; j < 4; j++) {
                const int p = lane + 32*j;
                float2 z = cmulf(acc[mm][j], sT[m*128 + p]);
                g_Z[((size_t)(b*MM + m)*WF + w)*HH + h0 + p] = z;
            }
        }
        __syncthreads();
    }
}

// ---------------- cmix: Yf[b,k,w,:] = sum_m C[k,m] * Z'[b,m,w,:] -----------------
// One block per (b,w): stage all 32 m-lines (h now spatial), GEMM to 64 k-lines.
#define CMIX_SMEM ((MM*HH + MM*KK) * 8)   // 114688 bytes
__global__ void k_cmix(const float* __restrict__ C_re, const float* __restrict__ C_im) {
    extern __shared__ float2 dyn2[];
    float2* sZ  = dyn2;             // [32][384]
    float2* sCt = dyn2 + MM*HH;     // [m][k] 32*64
    const int tid = threadIdx.x;
    const int b = blockIdx.x / WF;
    const int w = blockIdx.x % WF;

    for (int i = tid; i < MM*KK; i += 256) {
        const int m = i >> 6, k = i & 63;
        sCt[i] = make_float2(C_re[k*MM + m], C_im[k*MM + m]);
    }
    // stage Z lines: 32 lines x 192 float4
#pragma unroll
    for (int j = 0; j < 24; j++) {
        const int idx = tid + 256*j;               // < 6144
        const int line = idx / 192, pos = idx % 192;
        const float4* src = (const float4*)(g_Z + ((size_t)(b*MM + line)*WF + w)*HH);
        ((float4*)sZ)[idx] = src[pos];
    }
    __syncthreads();

#pragma unroll 1
    for (int it = 0; it < 12; it++) {
        const int idx = tid + 256*it;              // < 3072 = 16kt * 192ht
        const int kt = idx / 192, ht = idx % 192;
        const int k0 = kt*4, h0 = ht*2;
        float2 a00 = make_float2(0.f,0.f), a01 = a00, a10 = a00, a11 = a00;
        float2 a20 = a00, a21 = a00, a30 = a00, a31 = a00;
#pragma unroll
        for (int m = 0; m < MM; m++) {
            const float4 zz = *(const float4*)(sZ + m*384 + h0);
            const float2 z0 = make_float2(zz.x, zz.y);
            const float2 z1 = make_float2(zz.z, zz.w);
            const float4 ca = *(const float4*)(sCt + m*64 + k0);
            const float4 cb = *(const float4*)(sCt + m*64 + k0 + 2);
            const float2 c0 = make_float2(ca.x, ca.y);
            const float2 c1 = make_float2(ca.z, ca.w);
            const float2 c2 = make_float2(cb.x, cb.y);
            const float2 c3 = make_float2(cb.z, cb.w);
            cfma(a00, c0, z0); cfma(a01, c0, z1);
            cfma(a10, c1, z0); cfma(a11, c1, z1);
            cfma(a20, c2, z0); cfma(a21, c2, z1);
            cfma(a30, c3, z0); cfma(a31, c3, z1);
        }
        float4* dst0 = (float4*)(g_Yf + ((size_t)(b*KK + k0 + 0)*WF + w)*HH + h0);
        float4* dst1 = (float4*)(g_Yf + ((size_t)(b*KK + k0 + 1)*WF + w)*HH + h0);
        float4* dst2 = (float4*)(g_Yf + ((size_t)(b*KK + k0 + 2)*WF + w)*HH + h0);
        float4* dst3 = (float4*)(g_Yf + ((size_t)(b*KK + k0 + 3)*WF + w)*HH + h0);
        *dst0 = make_float4(a00.x, a00.y, a01.x, a01.y);
        *dst1 = make_float4(a10.x, a10.y, a11.x, a11.y);
        *dst2 = make_float4(a20.x, a20.y, a21.x, a21.y);
        *dst3 = make_float4(a30.x, a30.y, a31.x, a31.y);
    }
}

// ---------------- inverse rows: packed (2 output channels per complex IFFT) -----
__global__ void k_inv_p(float* __restrict__ y) {
    __shared__ float2 sa[4*LSTR], sb[4*LSTR], tw[384];
    for (int i = threadIdx.x; i < 384; i += 256) tw[i] = g_tw[i];
    const int l = threadIdx.x & 3, t = threadIdx.x >> 2;
    const int line = blockIdx.x*4 + l;
    const int h = line % 384;
    const int kp = (line / 384) & 31;
    const int b = line / (384*32);
    const size_t base1 = ((size_t)(b*KK + 2*kp)*WF)*HH + h;
    const size_t base2 = base1 + (size_t)WF*HH;
    float2* pa = sa + l*LSTR;
    float2* pb = sb + l*LSTR;
#pragma unroll
    for (int i = 0; i < 6; i++) {
        const int w = t + 64*i;
        const int wi = (w < WF) ? w : (384 - w);
        const float2 q1 = g_Yf[base1 + (size_t)wi*HH];
        const float2 q2 = g_Yf[base2 + (size_t)wi*HH];
        float2 z;
        if (w == 0 || w == 192) {
            z = make_float2(q1.x, q2.x);
        } else if (w < WF) {
            z = make_float2(q1.x - q2.y, q1.y + q2.x);
        } else {
            z = make_float2(q1.x + q2.y, q2.x - q1.y);
        }
        pa[w] = z;
    }
    fft384<1>(pa, pb, tw, t);
    const float sc = 1.f / (float)(HH*WW);
    float* o1 = y + ((size_t)(b*KK + 2*kp)*HH + h) * WW;
    float* o2 = o1 + (size_t)HH*WW;
#pragma unroll
    for (int i = 0; i < 6; i++) {
        const int j = t + 64*i;
        const float2 v = pb[j];
        o1[j] = v.x * sc;
        o2[j] = v.y * sc;
    }
}

// ---------------- launch ----------------
extern "C" void kernel_launch(void* const* d_in, const int* in_sizes, int n_in,
                              void* d_out, int out_size) {
    const float* x         = (const float*)d_in[0];
    const float* theta     = (const float*)d_in[1];
    const float* B_re      = (const float*)d_in[2];
    const float* B_im      = (const float*)d_in[3];
    const float* C_re      = (const float*)d_in[4];
    const float* C_im      = (const float*)d_in[5];
    const float* alpha_raw = (const float*)d_in[6];
    const float* beta      = (const float*)d_in[7];
    const float* log_dc    = (const float*)d_in[8];
    const float* log_tau   = (const float*)d_in[9];
    const float* log_scale = (const float*)d_in[10];
    const float* log_bw    = (const float*)d_in[11];
    float* y = (float*)d_out;

    cudaFuncSetAttribute(k_mixZ, cudaFuncAttributeMaxDynamicSharedMemorySize, 65536);
    cudaFuncSetAttribute(k_cmix, cudaFuncAttributeMaxDynamicSharedMemorySize, CMIX_SMEM);

    k_tw<<<1, 384>>>();
    k_stats1<<<512, 256>>>(x);
    k_stats2<<<1, 512>>>();
    k_fwd_u<<<(BB*CC*HH)/4, 256>>>(x);                  // 12288 blocks
    k_col<-1, 0><<<(BB*CC*WF)/4, 256>>>();              // 6176 blocks (fwd cols, Xr)
    k_mixZ<<<WF*3, 256, 49152>>>(B_re, B_im, theta, alpha_raw, beta,
                                 log_dc, log_tau, log_scale, log_bw);
    k_col<1, 2><<<(BB*MM*WF)/4, 256>>>();               // 12352 blocks (inv cols, Z)
    k_cmix<<<BB*WF, 256, CMIX_SMEM>>>(C_re, C_im);      // 1544 blocks
    k_inv_p<<<(BB*MM*HH)/4, 256>>>(y);                  // 24576 blocks
}

// round 6
// speedup vs baseline: 1.4606x; 1.0628x over previous
#include <cuda_runtime.h>
#include <math.h>

// Problem constants
#define BB 8
#define CC 16
#define MM 32
#define KK 64
#define HH 384
#define WW 384
#define WF 193

// ---------------- scratch ----------------
__device__ float2 g_Xr[(size_t)BB*CC*WF*HH];   // [b,c,w,h]
__device__ float2 g_Z [(size_t)BB*MM*WF*HH];   // [b,m,w,h]
__device__ float2 g_Yf[(size_t)BB*KK*WF*HH];   // [b,k,w,h]
__device__ float2 g_tw[384];
__device__ float2 g_part[512];
__device__ float2 g_stats[8];

__device__ __forceinline__ float2 cmulf(float2 a, float2 b) {
    return make_float2(a.x*b.x - a.y*b.y, a.x*b.y + a.y*b.x);
}
__device__ __forceinline__ void cfma(float2& acc, float2 a, float2 b) {
    acc.x += a.x*b.x; acc.x -= a.y*b.y;
    acc.y += a.x*b.y; acc.y += a.y*b.x;
}

// ---------------- small DFTs ----------------
template<int SIGN>
__device__ __forceinline__ void dft6(float2 v[6]) {
    const float S3 = 0.8660254037844386f * (float)SIGN;
    const float ct[6] = {1.f, 0.5f, -0.5f, -1.f, -0.5f, 0.5f};
    const float st[6] = {0.f, S3, S3, 0.f, -S3, -S3};
    float2 o[6];
#pragma unroll
    for (int r = 0; r < 6; r++) {
        float re = v[0].x, im = v[0].y;
#pragma unroll
        for (int j = 1; j < 6; j++) {
            const int k = (j*r) % 6;
            re += v[j].x*ct[k] - v[j].y*st[k];
            im += v[j].x*st[k] + v[j].y*ct[k];
        }
        o[r] = make_float2(re, im);
    }
#pragma unroll
    for (int r = 0; r < 6; r++) v[r] = o[r];
}

template<int SIGN>
__device__ __forceinline__ void dft8(float2 v[8]) {
    const float R2 = 0.70710678118654752f;
    const float S = (float)SIGN;
    const float ct[8] = {1.f, R2, 0.f, -R2, -1.f, -R2, 0.f, R2};
    const float st[8] = {0.f, R2*S, 1.f*S, R2*S, 0.f, -R2*S, -1.f*S, -R2*S};
    float2 o[8];
#pragma unroll
    for (int r = 0; r < 8; r++) {
        float re = v[0].x, im = v[0].y;
#pragma unroll
        for (int j = 1; j < 8; j++) {
            const int k = (j*r) & 7;
            re += v[j].x*ct[k] - v[j].y*st[k];
            im += v[j].x*st[k] + v[j].y*ct[k];
        }
        o[r] = make_float2(re, im);
    }
#pragma unroll
    for (int r = 0; r < 8; r++) v[r] = o[r];
}

// ---------------- 384-pt FFT, register in/out -----------------------------------
// Input: vin[6] = x[t + 64*j] per thread (t in [0,64)).
// Output: threads t<48 hold vout[r] = X[t + 48*r].
// Caller must __syncthreads() after staging tw before calling.
template<int SIGN>
__device__ __forceinline__ void fft384_rr(float2 vin[6], float2 vout[8],
                                          float2* pa, float2* pb,
                                          const float2* tw, int t) {
    // stage 1: radix-6 (registers -> pb)
    dft6<SIGN>(vin);
#pragma unroll
    for (int r = 0; r < 6; r++) {
        float2 w = tw[t*r];
        if (SIGN > 0) w.y = -w.y;
        pb[6*t + r] = cmulf(vin[r], w);
    }
    __syncthreads();
    // stage 2: radix-8 (pb -> pa)
    if (t < 48) {
        const int q = t % 6, p = t / 6;
        float2 v[8];
#pragma unroll
        for (int j = 0; j < 8; j++) v[j] = pb[q + 6*(p + 8*j)];
        dft8<SIGN>(v);
#pragma unroll
        for (int r = 0; r < 8; r++) {
            float2 w = tw[6*p*r];
            if (SIGN > 0) w.y = -w.y;
            pa[q + 6*(8*p + r)] = cmulf(v[r], w);
        }
    }
    __syncthreads();
    // stage 3: radix-8 (pa -> registers), twiddles = 1
    if (t < 48) {
#pragma unroll
        for (int j = 0; j < 8; j++) vout[j] = pa[t + 48*j];
        dft8<SIGN>(vout);
    }
}

#define LSTR 390

// ---------------- twiddle init ----------------
__global__ void k_tw() {
    int i = threadIdx.x;
    if (i < 384) {
        float s, c;
        sincosf(-6.28318530717958647692f * (float)i / 384.f, &s, &c);
        g_tw[i] = make_float2(c, s);
    }
}

// ---------------- stats ----------------
__global__ void k_stats1(const float* __restrict__ x) {
    const int b = blockIdx.x >> 6, sl = blockIdx.x & 63;
    const float4* p = (const float4*)x + (size_t)b*589824 + (size_t)sl*9216;
    float s = 0.f, q = 0.f;
    for (int i = threadIdx.x; i < 9216; i += 256) {
        float4 v = p[i];
        s += v.x + v.y + v.z + v.w;
        q += v.x*v.x + v.y*v.y + v.z*v.z + v.w*v.w;
    }
    __shared__ float rs[256], rq[256];
    rs[threadIdx.x] = s; rq[threadIdx.x] = q;
    __syncthreads();
    for (int o = 128; o > 0; o >>= 1) {
        if (threadIdx.x < o) { rs[threadIdx.x] += rs[threadIdx.x+o]; rq[threadIdx.x] += rq[threadIdx.x+o]; }
        __syncthreads();
    }
    if (threadIdx.x == 0) g_part[blockIdx.x] = make_float2(rs[0], rq[0]);
}

__global__ void k_stats2() {
    __shared__ float2 sp[512];
    sp[threadIdx.x] = g_part[threadIdx.x];
    __syncthreads();
    if (threadIdx.x < 8) {
        float s = 0.f, q = 0.f;
        for (int i = 0; i < 64; i++) { float2 v = sp[threadIdx.x*64 + i]; s += v.x; q += v.y; }
        const float Nb = (float)(CC*HH*WW);
        float mean = s / Nb;
        float var = q / Nb - mean*mean;
        g_stats[threadIdx.x] = make_float2(mean, rsqrtf(var + 1e-5f));
    }
}

// ---------------- forward rows (unpacked, reg in/out) ---------------------------
__global__ void k_fwd_u(const float* __restrict__ x) {
    __shared__ float2 sa[4*LSTR], sb[4*LSTR], tw[384];
    for (int i = threadIdx.x; i < 384; i += 256) tw[i] = g_tw[i];
    const int l = threadIdx.x & 3, t = threadIdx.x >> 2;
    const int line = blockIdx.x*4 + l;
    const int h = line % 384;
    const int c = (line / 384) & 15;
    const int b = line / (384*16);
    const float* xr = x + (((size_t)(b*CC + c)*HH + h) * WW);
    float2 vin[6], vout[8];
#pragma unroll
    for (int j = 0; j < 6; j++) vin[j] = make_float2(xr[t + 64*j], 0.f);
    __syncthreads();     // tw ready
    fft384_rr<-1>(vin, vout, sa + l*LSTR, sb + l*LSTR, tw, t);
    if (t < 48) {
        float2* dst = g_Xr + ((size_t)(b*CC + c)*WF)*HH + h;
#pragma unroll
        for (int r = 0; r < 8; r++) {
            const int n = t + 48*r;
            if (n < WF) dst[(size_t)n*HH] = vout[r];
        }
    }
}

// ---------------- column FFTs (WHICH: 0=g_Xr, 2=g_Z) ----------------------------
template<int SIGN, int WHICH>
__global__ void k_col() {
    __shared__ float2 sa[4*LSTR], sb[4*LSTR], tw[384];
    for (int i = threadIdx.x; i < 384; i += 256) tw[i] = g_tw[i];
    const int l = threadIdx.x & 3, t = threadIdx.x >> 2;
    const size_t line = (size_t)blockIdx.x*4 + l;
    float2* g = (WHICH == 0 ? g_Xr : g_Z) + line*HH;
    float2 vin[6], vout[8];
#pragma unroll
    for (int j = 0; j < 6; j++) vin[j] = g[t + 64*j];
    __syncthreads();
    fft384_rr<SIGN>(vin, vout, sa + l*LSTR, sb + l*LSTR, tw, t);
    if (t < 48) {
#pragma unroll
        for (int r = 0; r < 8; r++) g[t + 48*r] = vout[r];
    }
}

// ---------------- mixZ: Z = (B @ Xf_norm) * T ------------------------------------
__global__ void k_mixZ(const float* __restrict__ B_re, const float* __restrict__ B_im,
                       const float* __restrict__ theta, const float* __restrict__ alpha_raw,
                       const float* __restrict__ beta,  const float* __restrict__ log_dc,
                       const float* __restrict__ log_tau, const float* __restrict__ log_scale,
                       const float* __restrict__ log_bw) {
    extern __shared__ float2 dyn[];
    float2* sT = dyn;           // [32][128]
    float2* sX = dyn + 4096;    // [16][128]
    __shared__ float2 sBt[CC*MM];
    __shared__ float  sPar[MM][8];

    const int tid = threadIdx.x;
    const int w = blockIdx.x / 3;
    const int h0 = (blockIdx.x % 3) * 128;

    for (int i = tid; i < CC*MM; i += 256) {
        const int c = i >> 5, m = i & 31;
        sBt[i] = make_float2(B_re[m*CC + c], B_im[m*CC + c]);
    }
    if (tid < MM) {
        const int m = tid;
        float ar = alpha_raw[m];
        float spa = (ar > 20.f) ? ar : log1pf(expf(ar));
        float wc = expf(log_bw[m]);
        sPar[m][0] = spa;
        sPar[m][1] = beta[m];
        sPar[m][2] = expf(log_scale[m]);
        sPar[m][3] = expf(log_tau[m]);
        sPar[m][4] = expf(log_dc[m]);
        sPar[m][5] = 1.f / (wc*wc);
        sPar[m][6] = cosf(theta[m]);
        sPar[m][7] = sinf(theta[m]);
    }
    __syncthreads();

    const float TPN = 6.28318530717958647692f / 384.f;
    const float ox = (float)w * TPN;
    for (int e = tid; e < MM*128; e += 256) {
        const int m = e >> 7, p = e & 127, h = h0 + p;
        const float oy = (float)((h < 192) ? h : h - 384) * TPN;
        const float vd = sPar[m][6]*ox + sPar[m][7]*oy;
        const float w2 = ox*ox + oy*oy;
        const float wp2 = w2 - vd*vd;
        float Dre = sPar[m][0] + sPar[m][3]*wp2;
        float Dim = sPar[m][2]*vd - sPar[m][1];
        const float qq = w2 * sPar[m][5];
        const float q2 = qq*qq;
        const float bt = 1.f + q2*q2;
        Dre *= bt; Dim *= bt;
        const float inv = sPar[m][4] / (Dre*Dre + Dim*Dim);
        sT[e] = make_float2(Dre*inv, -Dim*inv);
    }
    __syncthreads();

    const int warp = tid >> 5, lane = tid & 31;
    const int m0 = warp * 4;
    const float HWf = (float)(HH*WW);

    for (int b = 0; b < BB; b++) {
        const float mean = g_stats[b].x, rstd = g_stats[b].y;
        for (int e = tid; e < CC*128; e += 256) {
            const int c = e >> 7, p = e & 127;
            float2 v = g_Xr[((size_t)(b*CC + c)*WF + w)*HH + h0 + p];
            if (w == 0 && (h0 + p) == 0) v.x -= mean * HWf;
            v.x *= rstd; v.y *= rstd;
            sX[e] = v;
        }
        __syncthreads();

        float2 acc[4][4];
#pragma unroll
        for (int mm = 0; mm < 4; mm++)
#pragma unroll
            for (int j = 0; j < 4; j++) acc[mm][j] = make_float2(0.f, 0.f);

#pragma unroll
        for (int c = 0; c < CC; c++) {
            float2 bv[4], xv[4];
#pragma unroll
            for (int mm = 0; mm < 4; mm++) bv[mm] = sBt[c*32 + m0 + mm];
#pragma unroll
            for (int j = 0; j < 4; j++) xv[j] = sX[c*128 + lane + 32*j];
#pragma unroll
            for (int mm = 0; mm < 4; mm++)
#pragma unroll
                for (int j = 0; j < 4; j++) cfma(acc[mm][j], bv[mm], xv[j]);
        }
#pragma unroll
        for (int mm = 0; mm < 4; mm++) {
            const int m = m0 + mm;
#pragma unroll
            for (int j = 0; j < 4; j++) {
                const int p = lane + 32*j;
                float2 z = cmulf(acc[mm][j], sT[m*128 + p]);
                g_Z[((size_t)(b*MM + m)*WF + w)*HH + h0 + p] = z;
            }
        }
        __syncthreads();
    }
}

// ---------------- cmix: Yf[b,k,w,h-tile] = sum_m C[k,m] * Z'[b,m,w,h-tile] ------
// One block per (b,w,h-tile of 128): smem 48KB -> 4 blocks/SM.
#define CMIX_HT 128
#define CMIX_SMEM ((MM*CMIX_HT + MM*KK) * 8)   // 49152 bytes
__global__ void k_cmix(const float* __restrict__ C_re, const float* __restrict__ C_im) {
    extern __shared__ float2 dyn2[];
    float2* sZ  = dyn2;               // [32][128]
    float2* sCt = dyn2 + MM*CMIX_HT;  // [m][k]
    const int tid = threadIdx.x;
    const int bw = blockIdx.x / 3;
    const int h0 = (blockIdx.x % 3) * CMIX_HT;
    const int b = bw / WF;
    const int w = bw % WF;

    for (int i = tid; i < MM*KK; i += 256) {
        const int m = i >> 6, k = i & 63;
        sCt[i] = make_float2(C_re[k*MM + m], C_im[k*MM + m]);
    }
    // stage Z tile: 32 lines x 64 float4
#pragma unroll
    for (int j = 0; j < 8; j++) {
        const int idx = tid + 256*j;               // < 2048
        const int line = idx >> 6, pos = idx & 63;
        const float4* src = (const float4*)(g_Z + ((size_t)(b*MM + line)*WF + w)*HH + h0);
        ((float4*)sZ)[idx] = src[pos];
    }
    __syncthreads();

#pragma unroll 1
    for (int it = 0; it < 4; it++) {
        const int idx = tid + 256*it;              // < 1024 = 16kt * 64ht
        const int kt = idx >> 6, ht = idx & 63;
        const int k0 = kt*4, hh = ht*2;
        float2 a00 = make_float2(0.f,0.f), a01 = a00, a10 = a00, a11 = a00;
        float2 a20 = a00, a21 = a00, a30 = a00, a31 = a00;
#pragma unroll
        for (int m = 0; m < MM; m++) {
            const float4 zz = *(const float4*)(sZ + m*CMIX_HT + hh);
            const float2 z0 = make_float2(zz.x, zz.y);
            const float2 z1 = make_float2(zz.z, zz.w);
            const float4 ca = *(const float4*)(sCt + m*64 + k0);
            const float4 cb = *(const float4*)(sCt + m*64 + k0 + 2);
            const float2 c0 = make_float2(ca.x, ca.y);
            const float2 c1 = make_float2(ca.z, ca.w);
            const float2 c2 = make_float2(cb.x, cb.y);
            const float2 c3 = make_float2(cb.z, cb.w);
            cfma(a00, c0, z0); cfma(a01, c0, z1);
            cfma(a10, c1, z0); cfma(a11, c1, z1);
            cfma(a20, c2, z0); cfma(a21, c2, z1);
            cfma(a30, c3, z0); cfma(a31, c3, z1);
        }
        const size_t base = ((size_t)(b*KK + k0)*WF + w)*HH + h0 + hh;
        *(float4*)(g_Yf + base)                    = make_float4(a00.x, a00.y, a01.x, a01.y);
        *(float4*)(g_Yf + base + (size_t)WF*HH)    = make_float4(a10.x, a10.y, a11.x, a11.y);
        *(float4*)(g_Yf + base + (size_t)2*WF*HH)  = make_float4(a20.x, a20.y, a21.x, a21.y);
        *(float4*)(g_Yf + base + (size_t)3*WF*HH)  = make_float4(a30.x, a30.y, a31.x, a31.y);
    }
}

// ---------------- inverse rows: packed pairs, reg in/out -------------------------
__global__ void k_inv_p(float* __restrict__ y) {
    __shared__ float2 sa[4*LSTR], sb[4*LSTR], tw[384];
    for (int i = threadIdx.x; i < 384; i += 256) tw[i] = g_tw[i];
    const int l = threadIdx.x & 3, t = threadIdx.x >> 2;
    const int line = blockIdx.x*4 + l;
    const int h = line % 384;
    const int kp = (line / 384) & 31;
    const int b = line / (384*32);
    const size_t base1 = ((size_t)(b*KK + 2*kp)*WF)*HH + h;
    const size_t base2 = base1 + (size_t)WF*HH;
    float2 vin[6], vout[8];
#pragma unroll
    for (int i = 0; i < 6; i++) {
        const int w = t + 64*i;
        const int wi = (w < WF) ? w : (384 - w);
        const float2 q1 = g_Yf[base1 + (size_t)wi*HH];
        const float2 q2 = g_Yf[base2 + (size_t)wi*HH];
        float2 z;
        if (w == 0 || w == 192) {
            z = make_float2(q1.x, q2.x);
        } else if (w < WF) {
            z = make_float2(q1.x - q2.y, q1.y + q2.x);
        } else {
            z = make_float2(q1.x + q2.y, q2.x - q1.y);
        }
        vin[i] = z;
    }
    __syncthreads();
    fft384_rr<1>(vin, vout, sa + l*LSTR, sb + l*LSTR, tw, t);
    if (t < 48) {
        const float sc = 1.f / (float)(HH*WW);
        float* o1 = y + ((size_t)(b*KK + 2*kp)*HH + h) * WW;
        float* o2 = o1 + (size_t)HH*WW;
#pragma unroll
        for (int r = 0; r < 8; r++) {
            const int n = t + 48*r;
            o1[n] = vout[r].x * sc;
            o2[n] = vout[r].y * sc;
        }
    }
}

// ---------------- launch ----------------
extern "C" void kernel_launch(void* const* d_in, const int* in_sizes, int n_in,
                              void* d_out, int out_size) {
    const float* x         = (const float*)d_in[0];
    const float* theta     = (const float*)d_in[1];
    const float* B_re      = (const float*)d_in[2];
    const float* B_im      = (const float*)d_in[3];
    const float* C_re      = (const float*)d_in[4];
    const float* C_im      = (const float*)d_in[5];
    const float* alpha_raw = (const float*)d_in[6];
    const float* beta      = (const float*)d_in[7];
    const float* log_dc    = (const float*)d_in[8];
    const float* log_tau   = (const float*)d_in[9];
    const float* log_scale = (const float*)d_in[10];
    const float* log_bw    = (const float*)d_in[11];
    float* y = (float*)d_out;

    cudaFuncSetAttribute(k_mixZ, cudaFuncAttributeMaxDynamicSharedMemorySize, 65536);
    cudaFuncSetAttribute(k_cmix, cudaFuncAttributeMaxDynamicSharedMemorySize, CMIX_SMEM);

    k_tw<<<1, 384>>>();
    k_stats1<<<512, 256>>>(x);
    k_stats2<<<1, 512>>>();
    k_fwd_u<<<(BB*CC*HH)/4, 256>>>(x);                  // 12288 blocks
    k_col<-1, 0><<<(BB*CC*WF)/4, 256>>>();              // 6176 blocks (fwd cols, Xr)
    k_mixZ<<<WF*3, 256, 49152>>>(B_re, B_im, theta, alpha_raw, beta,
                                 log_dc, log_tau, log_scale, log_bw);
    k_col<1, 2><<<(BB*MM*WF)/4, 256>>>();               // 12352 blocks (inv cols, Z)
    k_cmix<<<BB*WF*3, 256, CMIX_SMEM>>>(C_re, C_im);    // 4632 blocks
    k_inv_p<<<(BB*MM*HH)/4, 256>>>(y);                  // 24576 blocks
}

// round 8
// speedup vs baseline: 1.6581x; 1.1353x over previous
#include <cuda_runtime.h>
#include <math.h>

#define BB 8
#define CC 16
#define MM 32
#define KK 64
#define HH 384
#define WW 384
#define WF 193

// ---------------- scratch ----------------
__device__ float2 g_Xr[(size_t)BB*CC*WF*HH];   // [b,c,w,h]
__device__ float2 g_Yf[(size_t)BB*KK*WF*HH];   // [b,k,w,h]
__device__ float2 g_tw[384];
__device__ float2 g_part[512];
__device__ float2 g_stats[8];

__device__ __forceinline__ float2 cmulf(float2 a, float2 b) {
    return make_float2(a.x*b.x - a.y*b.y, a.x*b.y + a.y*b.x);
}
__device__ __forceinline__ void cfma(float2& acc, float2 a, float2 b) {
    acc.x += a.x*b.x; acc.x -= a.y*b.y;
    acc.y += a.x*b.y; acc.y += a.y*b.x;
}

// ---------------- small DFTs ----------------
template<int SIGN>
__device__ __forceinline__ void dft6(float2 v[6]) {
    const float S3 = 0.8660254037844386f * (float)SIGN;
    const float ct[6] = {1.f, 0.5f, -0.5f, -1.f, -0.5f, 0.5f};
    const float st[6] = {0.f, S3, S3, 0.f, -S3, -S3};
    float2 o[6];
#pragma unroll
    for (int r = 0; r < 6; r++) {
        float re = v[0].x, im = v[0].y;
#pragma unroll
        for (int j = 1; j < 6; j++) {
            const int k = (j*r) % 6;
            re += v[j].x*ct[k] - v[j].y*st[k];
            im += v[j].x*st[k] + v[j].y*ct[k];
        }
        o[r] = make_float2(re, im);
    }
#pragma unroll
    for (int r = 0; r < 6; r++) v[r] = o[r];
}

template<int SIGN>
__device__ __forceinline__ void dft8(float2 v[8]) {
    const float R2 = 0.70710678118654752f;
    const float S = (float)SIGN;
    const float ct[8] = {1.f, R2, 0.f, -R2, -1.f, -R2, 0.f, R2};
    const float st[8] = {0.f, R2*S, 1.f*S, R2*S, 0.f, -R2*S, -1.f*S, -R2*S};
    float2 o[8];
#pragma unroll
    for (int r = 0; r < 8; r++) {
        float re = v[0].x, im = v[0].y;
#pragma unroll
        for (int j = 1; j < 8; j++) {
            const int k = (j*r) & 7;
            re += v[j].x*ct[k] - v[j].y*st[k];
            im += v[j].x*st[k] + v[j].y*ct[k];
        }
        o[r] = make_float2(re, im);
    }
#pragma unroll
    for (int r = 0; r < 8; r++) v[r] = o[r];
}

#define LSTR 390

// reg-in / reg-out FFT (caller synced; pa/pb per-line regions)
template<int SIGN>
__device__ __forceinline__ void fft384_rr(float2 vin[6], float2 vout[8],
                                          float2* pa, float2* pb,
                                          const float2* tw, int t) {
    dft6<SIGN>(vin);
#pragma unroll
    for (int r = 0; r < 6; r++) {
        float2 w = tw[t*r];
        if (SIGN > 0) w.y = -w.y;
        pb[6*t + r] = cmulf(vin[r], w);
    }
    __syncthreads();
    if (t < 48) {
        const int q = t % 6, p = t / 6;
        float2 v[8];
#pragma unroll
        for (int j = 0; j < 8; j++) v[j] = pb[q + 6*(p + 8*j)];
        dft8<SIGN>(v);
#pragma unroll
        for (int r = 0; r < 8; r++) {
            float2 w = tw[6*p*r];
            if (SIGN > 0) w.y = -w.y;
            pa[q + 6*(8*p + r)] = cmulf(v[r], w);
        }
    }
    __syncthreads();
    if (t < 48) {
#pragma unroll
        for (int j = 0; j < 8; j++) vout[j] = pa[t + 48*j];
        dft8<SIGN>(vout);
    }
}

// ---------------- twiddle init ----------------
__global__ void k_tw() {
    int i = threadIdx.x;
    if (i < 384) {
        float s, c;
        sincosf(-6.28318530717958647692f * (float)i / 384.f, &s, &c);
        g_tw[i] = make_float2(c, s);
    }
}

// ---------------- stats ----------------
__global__ void k_stats1(const float* __restrict__ x) {
    const int b = blockIdx.x >> 6, sl = blockIdx.x & 63;
    const float4* p = (const float4*)x + (size_t)b*589824 + (size_t)sl*9216;
    float s = 0.f, q = 0.f;
    for (int i = threadIdx.x; i < 9216; i += 256) {
        float4 v = p[i];
        s += v.x + v.y + v.z + v.w;
        q += v.x*v.x + v.y*v.y + v.z*v.z + v.w*v.w;
    }
    __shared__ float rs[256], rq[256];
    rs[threadIdx.x] = s; rq[threadIdx.x] = q;
    __syncthreads();
    for (int o = 128; o > 0; o >>= 1) {
        if (threadIdx.x < o) { rs[threadIdx.x] += rs[threadIdx.x+o]; rq[threadIdx.x] += rq[threadIdx.x+o]; }
        __syncthreads();
    }
    if (threadIdx.x == 0) g_part[blockIdx.x] = make_float2(rs[0], rq[0]);
}

__global__ void k_stats2() {
    __shared__ float2 sp[512];
    sp[threadIdx.x] = g_part[threadIdx.x];
    __syncthreads();
    if (threadIdx.x < 8) {
        float s = 0.f, q = 0.f;
        for (int i = 0; i < 64; i++) { float2 v = sp[threadIdx.x*64 + i]; s += v.x; q += v.y; }
        const float Nb = (float)(CC*HH*WW);
        float mean = s / Nb;
        float var = q / Nb - mean*mean;
        g_stats[threadIdx.x] = make_float2(mean, rsqrtf(var + 1e-5f));
    }
}

// ---------------- forward rows: UNPACKED (known good) ----------------------------
__global__ void k_fwd_u(const float* __restrict__ x) {
    __shared__ float2 sa[4*LSTR], sb[4*LSTR], tw[384];
    for (int i = threadIdx.x; i < 384; i += 256) tw[i] = g_tw[i];
    const int l = threadIdx.x & 3, t = threadIdx.x >> 2;
    const int line = blockIdx.x*4 + l;
    const int h = line % 384;
    const int c = (line / 384) & 15;
    const int b = line / (384*16);
    const float* xr = x + (((size_t)(b*CC + c)*HH + h) * WW);
    float2 vin[6], vout[8];
#pragma unroll
    for (int j = 0; j < 6; j++) vin[j] = make_float2(xr[t + 64*j], 0.f);
    __syncthreads();
    fft384_rr<-1>(vin, vout, sa + l*LSTR, sb + l*LSTR, tw, t);
    if (t < 48) {
        float2* dst = g_Xr + ((size_t)(b*CC + c)*WF)*HH + h;
#pragma unroll
        for (int r = 0; r < 8; r++) {
            const int n = t + 48*r;
            if (n < WF) dst[(size_t)n*HH] = vout[r];
        }
    }
}

// ---------------- forward column FFTs on g_Xr ------------------------------------
__global__ void k_colf() {
    __shared__ float2 sa[4*LSTR], sb[4*LSTR], tw[384];
    for (int i = threadIdx.x; i < 384; i += 256) tw[i] = g_tw[i];
    const int l = threadIdx.x & 3, t = threadIdx.x >> 2;
    const size_t line = (size_t)blockIdx.x*4 + l;
    float2* g = g_Xr + line*HH;
    float2 vin[6], vout[8];
#pragma unroll
    for (int j = 0; j < 6; j++) vin[j] = g[t + 64*j];
    __syncthreads();
    fft384_rr<-1>(vin, vout, sa + l*LSTR, sb + l*LSTR, tw, t);
    if (t < 48) {
#pragma unroll
        for (int r = 0; r < 8; r++) g[t + 48*r] = vout[r];
    }
}

// ---------------- FUSED: (B@Xf)*T -> column IFFT -> C-GEMM -> Yf -----------------
#define FZ_ZM    0                      // sZm: [32][386] float2 = 98816
#define FZ_UNI   98816                  // union: sX [16][384] f2 (49152) / pp 16 x 390 f2 (49920)
#define FZ_CT    148736                 // sCt: [32][64] float2 = 16384
#define FZ_BT    165120                 // sBt: [16][32] float2 = 4096
#define FZ_TW    169216                 // tw: 384 float2 = 3072
#define FZ_PAR   172288                 // sPar: [32][8] float = 1024
#define FZ_TOTAL 173312

__global__ void __launch_bounds__(512, 1) k_fused(
    const float* __restrict__ B_re, const float* __restrict__ B_im,
    const float* __restrict__ C_re, const float* __restrict__ C_im,
    const float* __restrict__ theta, const float* __restrict__ alpha_raw,
    const float* __restrict__ beta,  const float* __restrict__ log_dc,
    const float* __restrict__ log_tau, const float* __restrict__ log_scale,
    const float* __restrict__ log_bw) {
    extern __shared__ char dynsm[];
    float2* sZm  = (float2*)(dynsm + FZ_ZM);
    float2* sX   = (float2*)(dynsm + FZ_UNI);
    float2* pp   = (float2*)(dynsm + FZ_UNI);
    float2* sCt  = (float2*)(dynsm + FZ_CT);
    float2* sBt  = (float2*)(dynsm + FZ_BT);
    float2* tw   = (float2*)(dynsm + FZ_TW);
    float*  sPar = (float*)(dynsm + FZ_PAR);

    const int tid = threadIdx.x;
    const int b = blockIdx.x / WF;
    const int w = blockIdx.x % WF;

    for (int i = tid; i < 384; i += 512) tw[i] = g_tw[i];
    for (int i = tid; i < CC*MM; i += 512) {
        const int c = i >> 5, m = i & 31;
        sBt[i] = make_float2(B_re[m*CC + c], B_im[m*CC + c]);
    }
    for (int i = tid; i < MM*KK; i += 512) {
        const int m = i >> 6, k = i & 63;
        sCt[i] = make_float2(C_re[k*MM + m], C_im[k*MM + m]);
    }
    if (tid < MM) {
        const int m = tid;
        float ar = alpha_raw[m];
        float spa = (ar > 20.f) ? ar : log1pf(expf(ar));
        float wc = expf(log_bw[m]);
        sPar[m*8+0] = spa;
        sPar[m*8+1] = beta[m];
        sPar[m*8+2] = expf(log_scale[m]);
        sPar[m*8+3] = expf(log_tau[m]);
        sPar[m*8+4] = expf(log_dc[m]);
        sPar[m*8+5] = 1.f / (wc*wc);
        sPar[m*8+6] = cosf(theta[m]);
        sPar[m*8+7] = sinf(theta[m]);
    }
    __syncthreads();

    // ---- T in registers: 3 items x (4m x 2h) ----
    const float TPN = 6.28318530717958647692f / 384.f;
    const float ox = (float)w * TPN;
    float2 Treg[24];
#pragma unroll
    for (int it = 0; it < 3; it++) {
        const int item = tid + 512*it;
        const int mq = item / 192, hp = item % 192;
#pragma unroll
        for (int mm = 0; mm < 4; mm++) {
            const int m = mq*4 + mm;
#pragma unroll
            for (int hh = 0; hh < 2; hh++) {
                const int h = 2*hp + hh;
                const float oy = (float)((h < 192) ? h : h - 384) * TPN;
                const float vd = sPar[m*8+6]*ox + sPar[m*8+7]*oy;
                const float w2 = ox*ox + oy*oy;
                const float wp2 = w2 - vd*vd;
                float Dre = sPar[m*8+0] + sPar[m*8+3]*wp2;
                float Dim = sPar[m*8+2]*vd - sPar[m*8+1];
                const float qq = w2 * sPar[m*8+5];
                const float q2 = qq*qq;
                const float bt = 1.f + q2*q2;
                Dre *= bt; Dim *= bt;
                const float inv = sPar[m*8+4] / (Dre*Dre + Dim*Dim);
                Treg[it*8 + mm*2 + hh] = make_float2(Dre*inv, -Dim*inv);
            }
        }
    }

    const float HWf = (float)(HH*WW);
    const float2 st = g_stats[b];
    const float mean = st.x, rstd = st.y;

    // ---- load Xf tile (normalized); DC fix for ALL channels ----
    {
        const float4* src = (const float4*)(g_Xr + ((size_t)(b*CC)*WF + w)*HH);
#pragma unroll
        for (int itr = 0; itr < 6; itr++) {
            const int idx = tid + 512*itr;           // < 3072
            const int c = idx / 192, q = idx % 192;
            float4 v = *(const float4*)((const char*)src + ((size_t)c*WF*HH + 2*q)*8);
            if (w == 0 && q == 0) v.x -= mean * HWf;   // h==0, every channel
            v.x *= rstd; v.y *= rstd; v.z *= rstd; v.w *= rstd;
            *(float4*)(sX + c*384 + 2*q) = v;
        }
    }
    __syncthreads();

    // ---- GEMM1 + T: Zspec[m][h] ----
#pragma unroll
    for (int it = 0; it < 3; it++) {
        const int item = tid + 512*it;
        const int mq = item / 192, hp = item % 192;
        float2 acc[4][2];
#pragma unroll
        for (int mm = 0; mm < 4; mm++) { acc[mm][0] = make_float2(0.f,0.f); acc[mm][1] = make_float2(0.f,0.f); }
#pragma unroll
        for (int c = 0; c < CC; c++) {
            const float4 xv = *(const float4*)(sX + c*384 + 2*hp);
            const float2 x0 = make_float2(xv.x, xv.y);
            const float2 x1 = make_float2(xv.z, xv.w);
            const float4 ba = *(const float4*)(sBt + c*32 + mq*4);
            const float4 bb = *(const float4*)(sBt + c*32 + mq*4 + 2);
            const float2 b0 = make_float2(ba.x, ba.y);
            const float2 b1 = make_float2(ba.z, ba.w);
            const float2 b2 = make_float2(bb.x, bb.y);
            const float2 b3 = make_float2(bb.z, bb.w);
            cfma(acc[0][0], b0, x0); cfma(acc[0][1], b0, x1);
            cfma(acc[1][0], b1, x0); cfma(acc[1][1], b1, x1);
            cfma(acc[2][0], b2, x0); cfma(acc[2][1], b2, x1);
            cfma(acc[3][0], b3, x0); cfma(acc[3][1], b3, x1);
        }
#pragma unroll
        for (int mm = 0; mm < 4; mm++) {
            const float2 z0 = cmulf(acc[mm][0], Treg[it*8 + mm*2 + 0]);
            const float2 z1 = cmulf(acc[mm][1], Treg[it*8 + mm*2 + 1]);
            *(float4*)(sZm + (mq*4 + mm)*386 + 2*hp) = make_float4(z0.x, z0.y, z1.x, z1.y);
        }
    }
    __syncthreads();

    // ---- column IFFT of 32 rows (4 groups of 8 lines) ----
    {
        const int l = tid & 7, t = tid >> 3;
        float2* pa = pp + l*LSTR;
        float2* pb = pp + 8*LSTR + l*LSTR;
#pragma unroll 1
        for (int g = 0; g < 4; g++) {
            float2* zrow = sZm + (g*8 + l)*386;
            float2 vin[6], vout[8];
#pragma unroll
            for (int j = 0; j < 6; j++) vin[j] = zrow[t + 64*j];
            fft384_rr<1>(vin, vout, pa, pb, tw, t);
            if (t < 48) {
#pragma unroll
                for (int r = 0; r < 8; r++) zrow[t + 48*r] = vout[r];
            }
            __syncthreads();
        }
    }

    // ---- GEMM2: Yf[k][h] = sum_m C[k][m] * Z[m][h] ----
#pragma unroll 1
    for (int it = 0; it < 6; it++) {
        const int item = tid + 512*it;               // < 3072
        const int kq = item / 192, hp = item % 192;
        float2 a00 = make_float2(0.f,0.f), a01 = a00, a10 = a00, a11 = a00;
        float2 a20 = a00, a21 = a00, a30 = a00, a31 = a00;
#pragma unroll
        for (int m = 0; m < MM; m++) {
            const float4 zz = *(const float4*)(sZm + m*386 + 2*hp);
            const float2 z0 = make_float2(zz.x, zz.y);
            const float2 z1 = make_float2(zz.z, zz.w);
            const float4 ca = *(const float4*)(sCt + m*64 + kq*4);
            const float4 cb = *(const float4*)(sCt + m*64 + kq*4 + 2);
            const float2 c0 = make_float2(ca.x, ca.y);
            const float2 c1 = make_float2(ca.z, ca.w);
            const float2 c2 = make_float2(cb.x, cb.y);
            const float2 c3 = make_float2(cb.z, cb.w);
            cfma(a00, c0, z0); cfma(a01, c0, z1);
            cfma(a10, c1, z0); cfma(a11, c1, z1);
            cfma(a20, c2, z0); cfma(a21, c2, z1);
            cfma(a30, c3, z0); cfma(a31, c3, z1);
        }
        const size_t base = ((size_t)(b*KK + kq*4)*WF + w)*HH + 2*hp;
        *(float4*)(g_Yf + base)                    = make_float4(a00.x, a00.y, a01.x, a01.y);
        *(float4*)(g_Yf + base + (size_t)WF*HH)    = make_float4(a10.x, a10.y, a11.x, a11.y);
        *(float4*)(g_Yf + base + (size_t)2*WF*HH)  = make_float4(a20.x, a20.y, a21.x, a21.y);
        *(float4*)(g_Yf + base + (size_t)3*WF*HH)  = make_float4(a30.x, a30.y, a31.x, a31.y);
    }
}

// ---------------- inverse rows: packed pairs, reg in/out -------------------------
__global__ void k_inv_p(float* __restrict__ y) {
    __shared__ float2 sa[4*LSTR], sb[4*LSTR], tw[384];
    for (int i = threadIdx.x; i < 384; i += 256) tw[i] = g_tw[i];
    const int l = threadIdx.x & 3, t = threadIdx.x >> 2;
    const int line = blockIdx.x*4 + l;
    const int h = line % 384;
    const int kp = (line / 384) & 31;
    const int b = line / (384*32);
    const size_t base1 = ((size_t)(b*KK + 2*kp)*WF)*HH + h;
    const size_t base2 = base1 + (size_t)WF*HH;
    float2 vin[6], vout[8];
#pragma unroll
    for (int i = 0; i < 6; i++) {
        const int w = t + 64*i;
        const int wi = (w < WF) ? w : (384 - w);
        const float2 q1 = g_Yf[base1 + (size_t)wi*HH];
        const float2 q2 = g_Yf[base2 + (size_t)wi*HH];
        float2 z;
        if (w == 0 || w == 192) {
            z = make_float2(q1.x, q2.x);
        } else if (w < WF) {
            z = make_float2(q1.x - q2.y, q1.y + q2.x);
        } else {
            z = make_float2(q1.x + q2.y, q2.x - q1.y);
        }
        vin[i] = z;
    }
    __syncthreads();
    fft384_rr<1>(vin, vout, sa + l*LSTR, sb + l*LSTR, tw, t);
    if (t < 48) {
        const float sc = 1.f / (float)(HH*WW);
        float* o1 = y + ((size_t)(b*KK + 2*kp)*HH + h) * WW;
        float* o2 = o1 + (size_t)HH*WW;
#pragma unroll
        for (int r = 0; r < 8; r++) {
            const int n = t + 48*r;
            o1[n] = vout[r].x * sc;
            o2[n] = vout[r].y * sc;
        }
    }
}

// ---------------- launch ----------------
extern "C" void kernel_launch(void* const* d_in, const int* in_sizes, int n_in,
                              void* d_out, int out_size) {
    const float* x         = (const float*)d_in[0];
    const float* theta     = (const float*)d_in[1];
    const float* B_re      = (const float*)d_in[2];
    const float* B_im      = (const float*)d_in[3];
    const float* C_re      = (const float*)d_in[4];
    const float* C_im      = (const float*)d_in[5];
    const float* alpha_raw = (const float*)d_in[6];
    const float* beta      = (const float*)d_in[7];
    const float* log_dc    = (const float*)d_in[8];
    const float* log_tau   = (const float*)d_in[9];
    const float* log_scale = (const float*)d_in[10];
    const float* log_bw    = (const float*)d_in[11];
    float* y = (float*)d_out;

    cudaFuncSetAttribute(k_fused, cudaFuncAttributeMaxDynamicSharedMemorySize, FZ_TOTAL);

    k_tw<<<1, 384>>>();
    k_stats1<<<512, 256>>>(x);
    k_stats2<<<1, 512>>>();
    k_fwd_u<<<(BB*CC*HH)/4, 256>>>(x);                  // 12288 blocks
    k_colf<<<(BB*CC*WF)/4, 256>>>();                    // 6176 blocks
    k_fused<<<BB*WF, 512, FZ_TOTAL>>>(B_re, B_im, C_re, C_im, theta, alpha_raw,
                                      beta, log_dc, log_tau, log_scale, log_bw);
    k_inv_p<<<(BB*MM*HH)/4, 256>>>(y);                  // 24576 blocks
}